// round 9
// baseline (speedup 1.0000x reference)
#include <cuda_runtime.h>
#include <math.h>

#define NB 8
#define NM 8192
#define ND 256
#define SLICE ((long)NB * NM * ND)   // 16,777,216 elements per hop slice

// Persistent scratch (device globals — no allocation allowed).
__device__ float g_ok0[NB * ND];      // o_k from hop 0
__device__ float g_ok1[NB * ND];      // o_k from hop 1
__device__ float g_logits[NB * NM];   // intermediate logits (hops 0,1)
__device__ float g_w[NB * NM];        // softmax * gp weights

// ---------------------------------------------------------------------------
// init: zero both o_k accumulators (must run every graph replay)
// ---------------------------------------------------------------------------
__global__ void init_kernel() {
    int i = blockIdx.x * blockDim.x + threadIdx.x;
    if (i < NB * ND) {
        g_ok0[i] = 0.0f;
        g_ok1[i] = 0.0f;
    }
}

// ---------------------------------------------------------------------------
// pass_a: logits[b,m] = gp[b,m] * dot(S[b,m,:], u[b,:])
//   u = q (+ ok0 if hop>=1) (+ ok1 if hop>=2)   -- fold fused in.
// 1 warp handles 4 rows (8 float4 in flight per lane = 128B).
// 8 warps/block -> 32 rows/block -> grid 2048.
// logits_out == nullptr -> write internal g_logits.
// ---------------------------------------------------------------------------
__global__ __launch_bounds__(256) void pass_a(const float* __restrict__ S,
                                              const float* __restrict__ gp,
                                              const float* __restrict__ q,
                                              int hop,
                                              float* logits_out) {
    __shared__ float us[ND];
    int tid = threadIdx.x;
    int b = blockIdx.x >> 8;                  // 256 blocks per batch
    float uv = q[b * ND + tid];
    if (hop >= 1) uv += g_ok0[b * ND + tid];
    if (hop >= 2) uv += g_ok1[b * ND + tid];
    us[tid] = uv;
    __syncthreads();

    int warp = tid >> 5;
    int lane = tid & 31;
    long row0 = (long)blockIdx.x * 32 + warp * 4;

    const float4* u4 = (const float4*)us;
    float4 ua = u4[lane];
    float4 uc = u4[lane + 32];

    float s[4];
    #pragma unroll
    for (int r = 0; r < 4; r++) {
        const float4* Sr = (const float4*)(S + (row0 + r) * ND);
        float4 a = Sr[lane];
        float4 c = Sr[lane + 32];
        s[r] = a.x * ua.x + a.y * ua.y + a.z * ua.z + a.w * ua.w
             + c.x * uc.x + c.y * uc.y + c.z * uc.z + c.w * uc.w;
    }

    #pragma unroll
    for (int off = 16; off; off >>= 1) {
        #pragma unroll
        for (int r = 0; r < 4; r++)
            s[r] += __shfl_xor_sync(0xffffffffu, s[r], off);
    }

    if (lane == 0) {
        float* dst = logits_out ? logits_out : g_logits;
        #pragma unroll
        for (int r = 0; r < 4; r++)
            dst[row0 + r] = gp[row0 + r] * s[r];
    }
}

// ---------------------------------------------------------------------------
// softmax over m per batch; writes w = p * gp (always) and p to p_out (last hop).
// logits_in == nullptr -> read internal g_logits.
// 1 block per batch, 1024 threads, 8 elems/thread.
// ---------------------------------------------------------------------------
__global__ __launch_bounds__(1024) void softmax_kernel(const float* logits_in,
                                                       const float* __restrict__ gp,
                                                       float* p_out) {
    __shared__ float red_max[32];
    __shared__ float red_sum[32];
    int b   = blockIdx.x;
    int tid = threadIdx.x;
    const float* logits = logits_in ? logits_in : g_logits;

    float l[8];
    float mx = -INFINITY;
    #pragma unroll
    for (int k = 0; k < 8; k++) {
        l[k] = logits[b * NM + tid + k * 1024];
        mx = fmaxf(mx, l[k]);
    }
    #pragma unroll
    for (int off = 16; off; off >>= 1)
        mx = fmaxf(mx, __shfl_xor_sync(0xffffffffu, mx, off));
    if ((tid & 31) == 0) red_max[tid >> 5] = mx;
    __syncthreads();
    if (tid < 32) {
        float v = red_max[tid];
        #pragma unroll
        for (int off = 16; off; off >>= 1)
            v = fmaxf(v, __shfl_xor_sync(0xffffffffu, v, off));
        red_max[tid] = v;
    }
    __syncthreads();
    mx = red_max[0];

    float sum = 0.0f;
    #pragma unroll
    for (int k = 0; k < 8; k++) {
        l[k] = __expf(l[k] - mx);
        sum += l[k];
    }
    #pragma unroll
    for (int off = 16; off; off >>= 1)
        sum += __shfl_xor_sync(0xffffffffu, sum, off);
    if ((tid & 31) == 0) red_sum[tid >> 5] = sum;
    __syncthreads();
    if (tid < 32) {
        float v = red_sum[tid];
        #pragma unroll
        for (int off = 16; off; off >>= 1)
            v += __shfl_xor_sync(0xffffffffu, v, off);
        red_sum[tid] = v;
    }
    __syncthreads();
    float inv = 1.0f / red_sum[0];

    #pragma unroll
    for (int k = 0; k < 8; k++) {
        int idx = b * NM + tid + k * 1024;
        float p = l[k] * inv;
        if (p_out) p_out[idx] = p;
        g_w[idx] = p * gp[idx];
    }
}

// ---------------------------------------------------------------------------
// pass_c: ok[b,d] += sum over 32-row chunk of w[b,m] * S[b,m,d]
// grid 2048 x 128 threads (4 warps): ~14 blocks/SM -> high occupancy.
// Each warp: 8 rows (warp-interleaved), 2 float4 per row = 16 float4 in flight.
// 4-warp smem reduction, then 2 atomics/thread (256/block).
// which: 0 -> g_ok0, 1 -> g_ok1.
// ---------------------------------------------------------------------------
__global__ __launch_bounds__(128) void pass_c(const float* __restrict__ S, int which) {
    __shared__ float ws[32];
    __shared__ float red[4][256];
    int tid  = threadIdx.x;
    int warp = tid >> 5;
    int lane = tid & 31;
    int b  = blockIdx.x >> 8;                 // 256 chunks per batch
    int m0 = (blockIdx.x & 255) * 32;

    if (tid < 32)
        ws[tid] = g_w[b * NM + m0 + tid];
    __syncthreads();

    const float* base = S + ((long)b * NM + m0) * ND;
    float4 accA = make_float4(0.f, 0.f, 0.f, 0.f);
    float4 accC = make_float4(0.f, 0.f, 0.f, 0.f);

    #pragma unroll
    for (int i = 0; i < 8; i++) {
        int r = warp + 4 * i;                 // warp-interleaved rows
        float wgt = ws[r];
        const float4* Sr = (const float4*)(base + (long)r * ND);
        float4 a = Sr[lane];
        float4 c = Sr[lane + 32];
        accA.x = fmaf(wgt, a.x, accA.x);
        accA.y = fmaf(wgt, a.y, accA.y);
        accA.z = fmaf(wgt, a.z, accA.z);
        accA.w = fmaf(wgt, a.w, accA.w);
        accC.x = fmaf(wgt, c.x, accC.x);
        accC.y = fmaf(wgt, c.y, accC.y);
        accC.z = fmaf(wgt, c.z, accC.z);
        accC.w = fmaf(wgt, c.w, accC.w);
    }

    ((float4*)&red[warp][lane * 4])[0]       = accA;
    ((float4*)&red[warp][128 + lane * 4])[0] = accC;
    __syncthreads();

    float* ok = which ? g_ok1 : g_ok0;
    float s0 = red[0][tid]       + red[1][tid]       + red[2][tid]       + red[3][tid];
    float s1 = red[0][tid + 128] + red[1][tid + 128] + red[2][tid + 128] + red[3][tid + 128];
    atomicAdd(&ok[b * ND + tid],       s0);
    atomicAdd(&ok[b * ND + tid + 128], s1);
}

// ---------------------------------------------------------------------------
// launcher — pure kernel launches, no host API calls (graph-capture safe).
// ---------------------------------------------------------------------------
extern "C" void kernel_launch(void* const* d_in, const int* in_sizes, int n_in,
                              void* d_out, int out_size) {
    // Map inputs by element count: 2048=query, 65536=gp, rest=m_story
    const float* q  = nullptr;
    const float* gp = nullptr;
    const float* S  = nullptr;
    for (int i = 0; i < n_in; i++) {
        if (in_sizes[i] == NB * ND)      q  = (const float*)d_in[i];
        else if (in_sizes[i] == NB * NM) gp = (const float*)d_in[i];
        else                             S  = (const float*)d_in[i];
    }

    float* out   = (float*)d_out;
    float* p_out = out;            // prob_soft   -> first 65536
    float* l_out = out + NB * NM;  // prob_logits -> second 65536

    init_kernel<<<2, 1024>>>();

    // hop 0
    pass_a<<<2048, 256>>>(S,             gp, q, 0, nullptr);
    softmax_kernel<<<NB, 1024>>>(nullptr, gp, nullptr);
    pass_c<<<2048, 128>>>(S + SLICE, 0);

    // hop 1
    pass_a<<<2048, 256>>>(S + SLICE,     gp, q, 1, nullptr);
    softmax_kernel<<<NB, 1024>>>(nullptr, gp, nullptr);
    pass_c<<<2048, 128>>>(S + 2 * SLICE, 1);

    // hop 2 — outputs only need logits + softmax; m_story[3] never touched.
    pass_a<<<2048, 256>>>(S + 2 * SLICE, gp, q, 2, l_out);
    softmax_kernel<<<NB, 1024>>>(l_out,   gp, p_out);
}

// round 16
// speedup vs baseline: 1.0685x; 1.0685x over previous
#include <cuda_runtime.h>
#include <math.h>

#define NB 8
#define NM 8192
#define ND 256
#define SLICE ((long)NB * NM * ND)   // 16,777,216 elements per hop slice

// Persistent scratch (device globals — no allocation allowed).
__device__ float g_ok0[NB * ND];      // o_k from hop 0
__device__ float g_ok1[NB * ND];      // o_k from hop 1
__device__ float g_logits[NB * NM];   // intermediate logits (hops 0,1)
__device__ float g_w[NB * NM];        // softmax * gp weights

// ---------------------------------------------------------------------------
// init: zero both o_k accumulators (must run every graph replay)
// ---------------------------------------------------------------------------
__global__ void init_kernel() {
    int i = blockIdx.x * blockDim.x + threadIdx.x;
    if (i < NB * ND) {
        g_ok0[i] = 0.0f;
        g_ok1[i] = 0.0f;
    }
}

// ---------------------------------------------------------------------------
// pass_a: logits[b,m] = gp[b,m] * dot(S[b,m,:], u[b,:])
//   u = q (+ ok0 if hop>=1) (+ ok1 if hop>=2)  -- fold fused in.
// 1 warp per 4 rows; all 8 float4 loads issued before FMAs (128B in flight
// per lane). 8 warps/block -> 32 rows/block -> grid 2048.
// logits_out == nullptr -> write internal g_logits.
// ---------------------------------------------------------------------------
__global__ __launch_bounds__(256) void pass_a(const float* __restrict__ S,
                                              const float* __restrict__ gp,
                                              const float* __restrict__ q,
                                              int hop,
                                              float* logits_out) {
    __shared__ float us[ND];
    int tid = threadIdx.x;
    int b = blockIdx.x >> 8;                  // 256 blocks per batch
    float uv = q[b * ND + tid];
    if (hop >= 1) uv += g_ok0[b * ND + tid];
    if (hop >= 2) uv += g_ok1[b * ND + tid];
    us[tid] = uv;
    __syncthreads();

    int warp = tid >> 5;
    int lane = tid & 31;
    long row0 = (long)blockIdx.x * 32 + warp * 4;

    const float4* u4 = (const float4*)us;
    float4 ua = u4[lane];
    float4 uc = u4[lane + 32];

    // Batch all 8 loads first (8 independent float4 LDGs in flight per lane)
    float4 a[4], c[4];
    #pragma unroll
    for (int r = 0; r < 4; r++) {
        const float4* Sr = (const float4*)(S + (row0 + r) * ND);
        a[r] = Sr[lane];
        c[r] = Sr[lane + 32];
    }

    float s[4];
    #pragma unroll
    for (int r = 0; r < 4; r++) {
        s[r] = a[r].x * ua.x + a[r].y * ua.y + a[r].z * ua.z + a[r].w * ua.w
             + c[r].x * uc.x + c[r].y * uc.y + c[r].z * uc.z + c[r].w * uc.w;
    }

    #pragma unroll
    for (int off = 16; off; off >>= 1) {
        #pragma unroll
        for (int r = 0; r < 4; r++)
            s[r] += __shfl_xor_sync(0xffffffffu, s[r], off);
    }

    if (lane == 0) {
        float* dst = logits_out ? logits_out : g_logits;
        #pragma unroll
        for (int r = 0; r < 4; r++)
            dst[row0 + r] = gp[row0 + r] * s[r];
    }
}

// ---------------------------------------------------------------------------
// softmax over m per batch; writes w = p * gp (always) and p to p_out (last hop).
// logits_in == nullptr -> read internal g_logits.
// 1 block per batch, 1024 threads, 8 elems/thread.
// ---------------------------------------------------------------------------
__global__ __launch_bounds__(1024) void softmax_kernel(const float* logits_in,
                                                       const float* __restrict__ gp,
                                                       float* p_out) {
    __shared__ float red_max[32];
    __shared__ float red_sum[32];
    int b   = blockIdx.x;
    int tid = threadIdx.x;
    const float* logits = logits_in ? logits_in : g_logits;

    float l[8];
    float mx = -INFINITY;
    #pragma unroll
    for (int k = 0; k < 8; k++) {
        l[k] = logits[b * NM + tid + k * 1024];
        mx = fmaxf(mx, l[k]);
    }
    #pragma unroll
    for (int off = 16; off; off >>= 1)
        mx = fmaxf(mx, __shfl_xor_sync(0xffffffffu, mx, off));
    if ((tid & 31) == 0) red_max[tid >> 5] = mx;
    __syncthreads();
    if (tid < 32) {
        float v = red_max[tid];
        #pragma unroll
        for (int off = 16; off; off >>= 1)
            v = fmaxf(v, __shfl_xor_sync(0xffffffffu, v, off));
        red_max[tid] = v;
    }
    __syncthreads();
    mx = red_max[0];

    float sum = 0.0f;
    #pragma unroll
    for (int k = 0; k < 8; k++) {
        l[k] = __expf(l[k] - mx);
        sum += l[k];
    }
    #pragma unroll
    for (int off = 16; off; off >>= 1)
        sum += __shfl_xor_sync(0xffffffffu, sum, off);
    if ((tid & 31) == 0) red_sum[tid >> 5] = sum;
    __syncthreads();
    if (tid < 32) {
        float v = red_sum[tid];
        #pragma unroll
        for (int off = 16; off; off >>= 1)
            v += __shfl_xor_sync(0xffffffffu, v, off);
        red_sum[tid] = v;
    }
    __syncthreads();
    float inv = 1.0f / red_sum[0];

    #pragma unroll
    for (int k = 0; k < 8; k++) {
        int idx = b * NM + tid + k * 1024;
        float p = l[k] * inv;
        if (p_out) p_out[idx] = p;
        g_w[idx] = p * gp[idx];
    }
}

// ---------------------------------------------------------------------------
// pass_c: ok[b,d] += sum over 64-row chunk of w[b,m] * S[b,m,d]
// 256 threads, grid 1024 (<=7 blocks/SM -> whole grid resident, one wave).
// Thread owns float4 column c = tid&63, row-group rg = tid>>6 (4 groups).
// 16 rows/thread in explicit 4-load batches (MLP_p1 = 4, regs ~32 -> high occ).
// 4-group smem reduction, 256 spread atomics per block.
// which: 0 -> g_ok0, 1 -> g_ok1.
// ---------------------------------------------------------------------------
__global__ __launch_bounds__(256) void pass_c(const float* __restrict__ S, int which) {
    __shared__ float ws[64];
    __shared__ float red[4][256];
    int tid = threadIdx.x;
    int b   = blockIdx.x >> 7;                // 128 chunks per batch
    int m0  = (blockIdx.x & 127) * 64;

    if (tid < 64)
        ws[tid] = g_w[b * NM + m0 + tid];
    __syncthreads();

    int c  = tid & 63;                        // float4 column within row
    int rg = tid >> 6;                        // row group 0..3
    const float4* S4 = (const float4*)(S + ((long)b * NM + m0) * ND);

    float4 acc = make_float4(0.f, 0.f, 0.f, 0.f);

    #pragma unroll 1
    for (int k = 0; k < 4; k++) {
        float4 v[4];
        float  wv[4];
        #pragma unroll
        for (int j = 0; j < 4; j++) {
            int r = rg + 4 * (k * 4 + j);     // rows rg, rg+4, ... (broadcast ws)
            v[j]  = S4[(long)r * 64 + c];
            wv[j] = ws[r];
        }
        #pragma unroll
        for (int j = 0; j < 4; j++) {
            acc.x = fmaf(wv[j], v[j].x, acc.x);
            acc.y = fmaf(wv[j], v[j].y, acc.y);
            acc.z = fmaf(wv[j], v[j].z, acc.z);
            acc.w = fmaf(wv[j], v[j].w, acc.w);
        }
    }

    ((float4*)red[rg])[c] = acc;
    __syncthreads();

    float* ok = which ? g_ok1 : g_ok0;
    float s = red[0][tid] + red[1][tid] + red[2][tid] + red[3][tid];
    atomicAdd(&ok[b * ND + tid], s);
}

// ---------------------------------------------------------------------------
// launcher — pure kernel launches, no host API calls (graph-capture safe).
// ---------------------------------------------------------------------------
extern "C" void kernel_launch(void* const* d_in, const int* in_sizes, int n_in,
                              void* d_out, int out_size) {
    // Map inputs by element count: 2048=query, 65536=gp, rest=m_story
    const float* q  = nullptr;
    const float* gp = nullptr;
    const float* S  = nullptr;
    for (int i = 0; i < n_in; i++) {
        if (in_sizes[i] == NB * ND)      q  = (const float*)d_in[i];
        else if (in_sizes[i] == NB * NM) gp = (const float*)d_in[i];
        else                             S  = (const float*)d_in[i];
    }

    float* out   = (float*)d_out;
    float* p_out = out;            // prob_soft   -> first 65536
    float* l_out = out + NB * NM;  // prob_logits -> second 65536

    init_kernel<<<2, 1024>>>();

    // hop 0
    pass_a<<<2048, 256>>>(S,             gp, q, 0, nullptr);
    softmax_kernel<<<NB, 1024>>>(nullptr, gp, nullptr);
    pass_c<<<1024, 256>>>(S + SLICE, 0);

    // hop 1
    pass_a<<<2048, 256>>>(S + SLICE,     gp, q, 1, nullptr);
    softmax_kernel<<<NB, 1024>>>(nullptr, gp, nullptr);
    pass_c<<<1024, 256>>>(S + 2 * SLICE, 1);

    // hop 2 — outputs only need logits + softmax; m_story[3] never touched.
    pass_a<<<2048, 256>>>(S + 2 * SLICE, gp, q, 2, l_out);
    softmax_kernel<<<NB, 1024>>>(l_out,   gp, p_out);
}